// round 3
// baseline (speedup 1.0000x reference)
#include <cuda_runtime.h>
#include <cuda_bf16.h>

// Problem constants
#define BB 8
#define NN 2048
#define FF 128
#define ROWS (BB*NN)            // 16384
#define ALPHA 0.2f

// ---------------- scratch (static device globals; no allocation) ----------
__device__ float    g_h[ROWS * FF];       // 8 MB  h = input @ W^T
__device__ float    g_src[ROWS];
__device__ float    g_dst[ROWS];
__device__ float    g_m[ROWS];            // row max (or -9e15 flag = uniform row)
__device__ float    g_rZ[ROWS];           // 1/Z  (or 1/N for uniform row)
__device__ unsigned g_mask[ROWS * (NN/32)]; // 4 MB adjacency bitmask

// ---------------- packed fp32x2 helpers (FFMA2 — PTX only) ----------------
__device__ __forceinline__ unsigned long long pack2(float x, float y) {
    unsigned long long r;
    asm("mov.b64 %0, {%1, %2};" : "=l"(r) : "f"(x), "f"(y));
    return r;
}
__device__ __forceinline__ void fma2(unsigned long long& d,
                                     unsigned long long a,
                                     unsigned long long b) {
    asm("fma.rn.f32x2 %0, %1, %2, %0;" : "+l"(d) : "l"(a), "l"(b));
}
__device__ __forceinline__ float2 unpack2(unsigned long long v) {
    float2 r;
    asm("mov.b64 {%0, %1}, %2;" : "=f"(r.x), "=f"(r.y) : "l"(v));
    return r;
}

// ===========================================================================
// Kernel 1: h = input @ W^T.   h[r][c] = sum_k input[r][k] * W[c][k]
// Block: 256 threads, tile 64 rows x 128 cols. K chunked by 32.
// ===========================================================================
__global__ __launch_bounds__(256) void k1_gemm(const float* __restrict__ input,
                                               const float* __restrict__ W) {
    __shared__ float shA[64][32];      // input tile
    __shared__ float shBt[32][128];    // W transposed chunk: shBt[k][c]

    const int tid  = threadIdx.x;
    const int warp = tid >> 5;
    const int lane = tid & 31;
    const int row0 = blockIdx.x * 64;
    const int c0   = lane * 4;

    unsigned long long acc[8][2];
    #pragma unroll
    for (int r = 0; r < 8; ++r) { acc[r][0] = 0ull; acc[r][1] = 0ull; }

    for (int kc = 0; kc < 4; ++kc) {
        __syncthreads();
        // load A tile: 64 x 32
        for (int v = tid; v < 64*32; v += 256) {
            int r = v >> 5, k = v & 31;
            shA[r][k] = input[(size_t)(row0 + r) * FF + kc*32 + k];
        }
        // load W chunk transposed: shBt[kk][c] = W[c][kc*32+kk]
        for (int v = tid; v < 32*128; v += 256) {
            int c = v & 127, kk = v >> 7;
            shBt[kk][c] = W[(size_t)c * FF + kc*32 + kk];
        }
        __syncthreads();

        #pragma unroll 4
        for (int k = 0; k < 32; ++k) {
            ulonglong2 bv = *(const ulonglong2*)&shBt[k][c0];
            #pragma unroll
            for (int r = 0; r < 8; ++r) {
                float a = shA[warp*8 + r][k];
                unsigned long long ap = pack2(a, a);
                fma2(acc[r][0], ap, bv.x);
                fma2(acc[r][1], ap, bv.y);
            }
        }
    }

    #pragma unroll
    for (int r = 0; r < 8; ++r) {
        int row = row0 + warp*8 + r;
        float2 p0 = unpack2(acc[r][0]);
        float2 p1 = unpack2(acc[r][1]);
        float4 o = make_float4(p0.x, p0.y, p1.x, p1.y);
        *(float4*)&g_h[(size_t)row * FF + c0] = o;
    }
}

// ===========================================================================
// Kernel 1b: src/dst dot products.  One warp per row.
// ===========================================================================
__global__ __launch_bounds__(256) void k1b_proj(const float* __restrict__ a_src,
                                                const float* __restrict__ a_dst) {
    const int warp = threadIdx.x >> 5;
    const int lane = threadIdx.x & 31;
    const int row  = blockIdx.x * 8 + warp;
    const float* hr = g_h + (size_t)row * FF;
    float s1 = 0.f, s2 = 0.f;
    #pragma unroll
    for (int c = lane; c < FF; c += 32) {
        float hv = hr[c];
        s1 += hv * __ldg(&a_src[c]);
        s2 += hv * __ldg(&a_dst[c]);
    }
    #pragma unroll
    for (int off = 16; off; off >>= 1) {
        s1 += __shfl_xor_sync(0xffffffffu, s1, off);
        s2 += __shfl_xor_sync(0xffffffffu, s2, off);
    }
    if (lane == 0) { g_src[row] = s1; g_dst[row] = s2; }
}

// ===========================================================================
// Kernel 2: scan adj row -> bitmask + softmax stats (m, 1/Z) via online pass.
// One warp per row; 8 rows per 256-thread block.
// ===========================================================================
__global__ __launch_bounds__(256) void k2_stats(const int* __restrict__ adj) {
    const int warp = threadIdx.x >> 5;
    const int lane = threadIdx.x & 31;
    const int row  = blockIdx.x * 8 + warp;        // 0..16383
    const int b    = row >> 11;
    const int i    = row & (NN-1);

    const int*   arow = adj + ((size_t)b * NN + i) * NN;
    const float* dstb = g_dst + b * NN;
    const float  srci = g_src[row];

    float m = -INFINITY, s = 0.f;
    for (int w = 0; w < NN/32; ++w) {
        int   j  = w*32 + lane;
        int   av = arow[j];
        float e  = srci + dstb[j];
        float lr = e > 0.f ? e : ALPHA * e;
        bool allowed = av > 0;
        unsigned bal = __ballot_sync(0xffffffffu, allowed);
        if (lane == 0) g_mask[(size_t)row * (NN/32) + w] = bal;
        if (allowed) {
            float nm = fmaxf(m, lr);
            s = s * __expf(m - nm) + __expf(lr - nm);
            m = nm;
        }
    }
    // warp reduce (m, s)
    #pragma unroll
    for (int off = 16; off; off >>= 1) {
        float mo = __shfl_xor_sync(0xffffffffu, m, off);
        float so = __shfl_xor_sync(0xffffffffu, s, off);
        float M  = fmaxf(m, mo);
        float sn = 0.f;
        if (m  > -INFINITY) sn += s  * __expf(m  - M);
        if (mo > -INFINITY) sn += so * __expf(mo - M);
        m = M; s = sn;
    }
    if (lane == 0) {
        if (m == -INFINITY) {            // no neighbors: softmax over NEG_INF row = uniform
            g_m[row]  = -9e15f;          // flag
            g_rZ[row] = 1.0f / (float)NN;
        } else {
            g_m[row]  = m;
            g_rZ[row] = 1.0f / s;
        }
    }
    if (m == -INFINITY) {                // all lanes agree post-reduce
        g_mask[(size_t)row * (NN/32) + lane]      = 0xffffffffu;
        g_mask[(size_t)row * (NN/32) + 32 + lane] = 0xffffffffu;
    }
}

// ===========================================================================
// Kernel 3: out = ELU( att @ h ).  Fused: never materializes att.
// Block: 128 threads, tile TI=64 rows x all 128 feats; loop j in tiles of 32.
// Thread = (ig in 0..7 -> 8 rows) x (fg in 0..15 -> 8 feats).
// Weights stored in smem pre-duplicated as {w,w} u64 for FFMA2.
// ===========================================================================
__global__ __launch_bounds__(128) void k3_agg(float* __restrict__ out) {
    __shared__ float              sh_h[32][128];     // 16 KB   h tile (j x f)
    __shared__ unsigned long long sh_wp[64][32];     // 16 KB   {w,w} (i x j)
    __shared__ float sh_src[64], sh_m[64], sh_rZ[64];
    __shared__ float sh_dst[32];
    __shared__ unsigned sh_mw[64];

    const int tid  = threadIdx.x;
    const int row0 = blockIdx.x * 64;
    const int b    = row0 >> 11;
    const int ig   = tid >> 4;        // 0..7
    const int fg   = tid & 15;        // 0..15
    const int f0   = fg * 8;

    if (tid < 64) {
        sh_src[tid] = g_src[row0 + tid];
        sh_m[tid]   = g_m[row0 + tid];
        sh_rZ[tid]  = g_rZ[row0 + tid];
    }

    unsigned long long acc[8][4];
    #pragma unroll
    for (int r = 0; r < 8; ++r)
        #pragma unroll
        for (int p = 0; p < 4; ++p) acc[r][p] = 0ull;

    for (int jt = 0; jt < NN/32; ++jt) {
        const int j0 = jt * 32;
        __syncthreads();   // protect smem from previous tile's readers

        // ---- load h tile (coalesced float4), dst slice, mask words ----
        const float* hb = g_h + ((size_t)b * NN + j0) * FF;
        #pragma unroll
        for (int v = tid; v < 32*32; v += 128) {
            int j = v >> 5, c4 = v & 31;
            ((float4*)sh_h[j])[c4] = ((const float4*)(hb + (size_t)j * FF))[c4];
        }
        if (tid < 32)       sh_dst[tid]     = g_dst[b * NN + j0 + tid];
        else if (tid < 96)  sh_mw[tid - 32] = g_mask[(size_t)(row0 + tid - 32) * (NN/32) + jt];
        __syncthreads();

        // ---- compute duplicated weights: thread = (j, 16 i's) ----
        {
            const int j   = tid & 31;
            const int ii0 = (tid >> 5) * 16;
            const float dj = sh_dst[j];
            #pragma unroll 4
            for (int ii = 0; ii < 16; ++ii) {
                int i = ii0 + ii;
                unsigned bit = (sh_mw[i] >> j) & 1u;
                float mi = sh_m[i];
                float rz = sh_rZ[i];
                float e  = sh_src[i] + dj;
                float lr = e > 0.f ? e : ALPHA * e;
                float w  = (mi < -1e14f) ? rz : __expf(lr - mi) * rz;  // uniform flag
                w = bit ? w : 0.f;
                sh_wp[i][j] = pack2(w, w);
            }
        }
        __syncthreads();

        // ---- FMA phase: 32 j x (8 rows x 8 feats) via FFMA2 ----
        #pragma unroll 4
        for (int j = 0; j < 32; ++j) {
            ulonglong2 h0 = *(const ulonglong2*)&sh_h[j][f0];
            ulonglong2 h1 = *(const ulonglong2*)&sh_h[j][f0 + 4];
            #pragma unroll
            for (int r = 0; r < 8; ++r) {
                unsigned long long wp = sh_wp[ig*8 + r][j];
                fma2(acc[r][0], wp, h0.x);
                fma2(acc[r][1], wp, h0.y);
                fma2(acc[r][2], wp, h1.x);
                fma2(acc[r][3], wp, h1.y);
            }
        }
    }

    // ---- epilogue: ELU + store ----
    #pragma unroll
    for (int r = 0; r < 8; ++r) {
        int row = row0 + ig*8 + r;
        float2 p0 = unpack2(acc[r][0]);
        float2 p1 = unpack2(acc[r][1]);
        float2 p2 = unpack2(acc[r][2]);
        float2 p3 = unpack2(acc[r][3]);
        float v[8] = {p0.x, p0.y, p1.x, p1.y, p2.x, p2.y, p3.x, p3.y};
        #pragma unroll
        for (int q = 0; q < 8; ++q)
            v[q] = v[q] > 0.f ? v[q] : (__expf(v[q]) - 1.0f);   // ELU
        float4 o0 = make_float4(v[0], v[1], v[2], v[3]);
        float4 o1 = make_float4(v[4], v[5], v[6], v[7]);
        *(float4*)&out[(size_t)row * FF + f0]     = o0;
        *(float4*)&out[(size_t)row * FF + f0 + 4] = o1;
    }
}

// ===========================================================================
extern "C" void kernel_launch(void* const* d_in, const int* in_sizes, int n_in,
                              void* d_out, int out_size) {
    const float* input = (const float*)d_in[0];   // [8,2048,128] f32
    const int*   adj   = (const int*)  d_in[1];   // [8,2048,2048] i32
    const float* W     = (const float*)d_in[2];   // [128,128] f32
    const float* a_src = (const float*)d_in[3];   // [128,1] f32
    const float* a_dst = (const float*)d_in[4];   // [128,1] f32
    float* out = (float*)d_out;                   // [8,2048,128] f32

    k1_gemm<<<ROWS/64, 256>>>(input, W);
    k1b_proj<<<ROWS/8, 256>>>(a_src, a_dst);
    k2_stats<<<ROWS/8, 256>>>(adj);
    k3_agg<<<ROWS/64, 128>>>(out);
}